// round 6
// baseline (speedup 1.0000x reference)
#include <cuda_runtime.h>
#include <math.h>

// Problem constants (fixed by the dataset)
#define B_    256
#define S_    196
#define RNN_  1024
#define ATTH_ 512
#define NSPLIT 7
#define SCHUNK 28   // 196 / 7
#define KSPLIT 2

// Scratch (allocation-free: __device__ globals)
__device__ float g_att_h_part[KSPLIT * B_ * ATTH_];  // 1 MB  (k1 partials)
__device__ float g_scores[B_ * S_];                  // 200 KB
__device__ float g_part[NSPLIT * B_ * RNN_];         // 7 MB  (k3 partials)

// ---------------------------------------------------------------------------
// HW tanh: MUFU.TANH, single instruction, abs err ~5e-4 (scores only feed a
// softmax; resulting output rel err ~1e-4, threshold is 1e-3).
// ---------------------------------------------------------------------------
__device__ __forceinline__ float tanh_approx(float x)
{
    float y;
    asm("tanh.approx.f32 %0, %1;" : "=f"(y) : "f"(x));
    return y;
}

// ---------------------------------------------------------------------------
// K1: partial att_h: part[kz][b][a] = sum_{k in half kz} h[b,k] * W[a,k]
// 32x32 tiles, BK=32, split-k=2, double-buffered smem.
// grid = (16, 8, 2) = 256 blocks, 256 threads, 2x2 microtile.
// ---------------------------------------------------------------------------
__global__ __launch_bounds__(256) void k1_h2att(
    const float* __restrict__ h, const float* __restrict__ w,
    float* __restrict__ part)
{
    __shared__ float sh[2][32][34];
    __shared__ float sw[2][32][34];

    const int t  = threadIdx.x;
    const int a0 = blockIdx.x * 32;
    const int b0 = blockIdx.y * 32;
    const int kz = blockIdx.z;
    const int tx = t & 15;
    const int ty = t >> 4;
    const int lr = t >> 3;
    const int lc = (t & 7) * 4;

    const float* hrow = &h[(size_t)(b0 + lr) * RNN_ + (size_t)kz * (RNN_ / KSPLIT) + lc];
    const float* wrow = &w[(size_t)(a0 + lr) * RNN_ + (size_t)kz * (RNN_ / KSPLIT) + lc];

    float4 hv = *(const float4*)hrow;
    float4 wv = *(const float4*)wrow;
    sh[0][lc + 0][lr] = hv.x; sh[0][lc + 1][lr] = hv.y;
    sh[0][lc + 2][lr] = hv.z; sh[0][lc + 3][lr] = hv.w;
    sw[0][lc + 0][lr] = wv.x; sw[0][lc + 1][lr] = wv.y;
    sw[0][lc + 2][lr] = wv.z; sw[0][lc + 3][lr] = wv.w;
    __syncthreads();

    float acc00 = 0.f, acc01 = 0.f, acc10 = 0.f, acc11 = 0.f;

    const int NT = RNN_ / KSPLIT / 32;   // 16 k-tiles
    #pragma unroll
    for (int kt = 0; kt < NT; kt++) {
        const int buf = kt & 1;
        if (kt + 1 < NT) {
            hv = *(const float4*)(hrow + (kt + 1) * 32);
            wv = *(const float4*)(wrow + (kt + 1) * 32);
        }
        #pragma unroll
        for (int kk = 0; kk < 32; kk++) {
            float2 hb = *(const float2*)&sh[buf][kk][ty * 2];
            float2 wb = *(const float2*)&sw[buf][kk][tx * 2];
            acc00 += hb.x * wb.x;
            acc01 += hb.x * wb.y;
            acc10 += hb.y * wb.x;
            acc11 += hb.y * wb.y;
        }
        __syncthreads();
        if (kt + 1 < NT) {
            const int nb = buf ^ 1;
            sh[nb][lc + 0][lr] = hv.x; sh[nb][lc + 1][lr] = hv.y;
            sh[nb][lc + 2][lr] = hv.z; sh[nb][lc + 3][lr] = hv.w;
            sw[nb][lc + 0][lr] = wv.x; sw[nb][lc + 1][lr] = wv.y;
            sw[nb][lc + 2][lr] = wv.z; sw[nb][lc + 3][lr] = wv.w;
            __syncthreads();
        }
    }

    const int bb = b0 + ty * 2;
    const int aa = a0 + tx * 2;
    float* op = part + (size_t)kz * B_ * ATTH_;
    op[(size_t)bb * ATTH_ + aa]           = acc00;
    op[(size_t)bb * ATTH_ + aa + 1]       = acc01;
    op[(size_t)(bb + 1) * ATTH_ + aa]     = acc10;
    op[(size_t)(bb + 1) * ATTH_ + aa + 1] = acc11;
}

// ---------------------------------------------------------------------------
// K2a: scores[b,s] = sum_a tanh(p[b,s,a] + att_h[b,a]) * w_alpha[a]
// att_h assembled in smem from the two k1 partials + bias.
// grid = (B, 4), 256 threads; warp processes two s-rows (8 loads in flight).
// ---------------------------------------------------------------------------
__global__ __launch_bounds__(256) void k2a_scores(
    const float* __restrict__ p, const float* __restrict__ att_h_part,
    const float* __restrict__ bias, const float* __restrict__ w_alpha,
    float* __restrict__ scores)
{
    const int b     = blockIdx.x;
    const int chunk = blockIdx.y;
    const int t     = threadIdx.x;

    __shared__ float4 ah4[ATTH_ / 4];
    __shared__ float4 wa4[ATTH_ / 4];
    {
        const float4* p0 = (const float4*)(att_h_part + (size_t)b * ATTH_);
        const float4* p1 = (const float4*)(att_h_part + (size_t)(B_ + b) * ATTH_);
        const float4* bz = (const float4*)bias;
        for (int i = t; i < ATTH_ / 4; i += 256) {
            float4 x = p0[i], y = p1[i], z = bz[i];
            ah4[i] = make_float4(x.x + y.x + z.x, x.y + y.y + z.y,
                                 x.z + y.z + z.z, x.w + y.w + z.w);
            wa4[i] = ((const float4*)w_alpha)[i];
        }
    }
    __syncthreads();

    const int warp = t >> 5, lane = t & 31;
    const int s_lo = chunk * 49;

    for (int pair = warp; pair < 24; pair += 8) {
        const int s = s_lo + pair * 2;
        const float4* ps0 = (const float4*)(p + ((size_t)b * S_ + s) * ATTH_);
        const float4* ps1 = ps0 + ATTH_ / 4;

        float4 u0 = __ldcs(&ps0[lane]);
        float4 u1 = __ldcs(&ps0[lane + 32]);
        float4 u2 = __ldcs(&ps0[lane + 64]);
        float4 u3 = __ldcs(&ps0[lane + 96]);
        float4 q0 = __ldcs(&ps1[lane]);
        float4 q1 = __ldcs(&ps1[lane + 32]);
        float4 q2 = __ldcs(&ps1[lane + 64]);
        float4 q3 = __ldcs(&ps1[lane + 96]);

        float accA = 0.f, accB = 0.f;
        {
            float4 a = ah4[lane],      wv = wa4[lane];
            accA += tanh_approx(u0.x + a.x) * wv.x + tanh_approx(u0.y + a.y) * wv.y
                  + tanh_approx(u0.z + a.z) * wv.z + tanh_approx(u0.w + a.w) * wv.w;
            accB += tanh_approx(q0.x + a.x) * wv.x + tanh_approx(q0.y + a.y) * wv.y
                  + tanh_approx(q0.z + a.z) * wv.z + tanh_approx(q0.w + a.w) * wv.w;
        }
        {
            float4 a = ah4[lane + 32], wv = wa4[lane + 32];
            accA += tanh_approx(u1.x + a.x) * wv.x + tanh_approx(u1.y + a.y) * wv.y
                  + tanh_approx(u1.z + a.z) * wv.z + tanh_approx(u1.w + a.w) * wv.w;
            accB += tanh_approx(q1.x + a.x) * wv.x + tanh_approx(q1.y + a.y) * wv.y
                  + tanh_approx(q1.z + a.z) * wv.z + tanh_approx(q1.w + a.w) * wv.w;
        }
        {
            float4 a = ah4[lane + 64], wv = wa4[lane + 64];
            accA += tanh_approx(u2.x + a.x) * wv.x + tanh_approx(u2.y + a.y) * wv.y
                  + tanh_approx(u2.z + a.z) * wv.z + tanh_approx(u2.w + a.w) * wv.w;
            accB += tanh_approx(q2.x + a.x) * wv.x + tanh_approx(q2.y + a.y) * wv.y
                  + tanh_approx(q2.z + a.z) * wv.z + tanh_approx(q2.w + a.w) * wv.w;
        }
        {
            float4 a = ah4[lane + 96], wv = wa4[lane + 96];
            accA += tanh_approx(u3.x + a.x) * wv.x + tanh_approx(u3.y + a.y) * wv.y
                  + tanh_approx(u3.z + a.z) * wv.z + tanh_approx(u3.w + a.w) * wv.w;
            accB += tanh_approx(q3.x + a.x) * wv.x + tanh_approx(q3.y + a.y) * wv.y
                  + tanh_approx(q3.z + a.z) * wv.z + tanh_approx(q3.w + a.w) * wv.w;
        }
        #pragma unroll
        for (int o = 16; o; o >>= 1) {
            accA += __shfl_xor_sync(0xffffffffu, accA, o);
            accB += __shfl_xor_sync(0xffffffffu, accB, o);
        }
        if (lane == 0) {
            scores[(size_t)b * S_ + s]     = accA;
            scores[(size_t)b * S_ + s + 1] = accB;
        }
    }

    // tail row (chunk-local row 48) by warp 0
    if (warp == 0) {
        const int s = s_lo + 48;
        const float4* ps = (const float4*)(p + ((size_t)b * S_ + s) * ATTH_);
        float4 v0 = __ldcs(&ps[lane]);
        float4 v1 = __ldcs(&ps[lane + 32]);
        float4 v2 = __ldcs(&ps[lane + 64]);
        float4 v3 = __ldcs(&ps[lane + 96]);
        float acc = 0.f;
        {
            float4 a = ah4[lane],      wv = wa4[lane];
            acc += tanh_approx(v0.x + a.x) * wv.x + tanh_approx(v0.y + a.y) * wv.y
                 + tanh_approx(v0.z + a.z) * wv.z + tanh_approx(v0.w + a.w) * wv.w;
        }
        {
            float4 a = ah4[lane + 32], wv = wa4[lane + 32];
            acc += tanh_approx(v1.x + a.x) * wv.x + tanh_approx(v1.y + a.y) * wv.y
                 + tanh_approx(v1.z + a.z) * wv.z + tanh_approx(v1.w + a.w) * wv.w;
        }
        {
            float4 a = ah4[lane + 64], wv = wa4[lane + 64];
            acc += tanh_approx(v2.x + a.x) * wv.x + tanh_approx(v2.y + a.y) * wv.y
                 + tanh_approx(v2.z + a.z) * wv.z + tanh_approx(v2.w + a.w) * wv.w;
        }
        {
            float4 a = ah4[lane + 96], wv = wa4[lane + 96];
            acc += tanh_approx(v3.x + a.x) * wv.x + tanh_approx(v3.y + a.y) * wv.y
                 + tanh_approx(v3.z + a.z) * wv.z + tanh_approx(v3.w + a.w) * wv.w;
        }
        #pragma unroll
        for (int o = 16; o; o >>= 1)
            acc += __shfl_xor_sync(0xffffffffu, acc, o);
        if (lane == 0) scores[(size_t)b * S_ + s] = acc;
    }
}

// ---------------------------------------------------------------------------
// K3a: partial weighted sums with fused (recomputed, deterministic) softmax.
// grid = (B, NSPLIT) = 1792 blocks, 128 threads; thread owns TWO float4 cols.
// ---------------------------------------------------------------------------
__global__ __launch_bounds__(128) void k3a_partial(
    const float* __restrict__ att, const float* __restrict__ scores,
    float* __restrict__ part)
{
    const int b     = blockIdx.x;
    const int split = blockIdx.y;
    const int t     = threadIdx.x;
    const int s_lo  = split * SCHUNK;

    __shared__ float es[S_];
    __shared__ float red[128];
    __shared__ float w_s[SCHUNK];

    float v0 = (t < S_)       ? scores[(size_t)b * S_ + t]       : -INFINITY;
    float v1 = (t + 128 < S_) ? scores[(size_t)b * S_ + t + 128] : -INFINITY;
    red[t] = fmaxf(v0, v1);
    __syncthreads();
    #pragma unroll
    for (int o = 64; o; o >>= 1) {
        if (t < o) red[t] = fmaxf(red[t], red[t + o]);
        __syncthreads();
    }
    const float m = red[0];
    __syncthreads();
    float e0 = (t < S_)       ? __expf(v0 - m) : 0.f;
    float e1 = (t + 128 < S_) ? __expf(v1 - m) : 0.f;
    if (t < S_)       es[t]       = e0;
    if (t + 128 < S_) es[t + 128] = e1;
    red[t] = e0 + e1;
    __syncthreads();
    #pragma unroll
    for (int o = 64; o; o >>= 1) {
        if (t < o) red[t] += red[t + o];
        __syncthreads();
    }
    const float inv = 1.f / red[0];
    __syncthreads();
    if (t < SCHUNK) w_s[t] = es[s_lo + t] * inv;
    __syncthreads();

    const float4* ap = (const float4*)(att + ((size_t)b * S_ + s_lo) * RNN_);
    float4 acc0 = make_float4(0.f, 0.f, 0.f, 0.f);
    float4 acc1 = make_float4(0.f, 0.f, 0.f, 0.f);
    #pragma unroll 7
    for (int s = 0; s < SCHUNK; s++) {
        const float w = w_s[s];
        const float4 va = __ldcs(&ap[(size_t)s * (RNN_ / 4) + t]);
        const float4 vb = __ldcs(&ap[(size_t)s * (RNN_ / 4) + t + 128]);
        acc0.x += w * va.x; acc0.y += w * va.y;
        acc0.z += w * va.z; acc0.w += w * va.w;
        acc1.x += w * vb.x; acc1.y += w * vb.y;
        acc1.z += w * vb.z; acc1.w += w * vb.w;
    }
    float4* op = (float4*)(part + ((size_t)split * B_ + b) * RNN_);
    op[t]       = acc0;
    op[t + 128] = acc1;
}

// ---------------------------------------------------------------------------
// K3b: out[b,d] = sum_split part[split][b][d]   (deterministic reduce)
// scalar-float granularity: 262144 threads (~55 warps/SM) for latency hiding.
// ---------------------------------------------------------------------------
__global__ __launch_bounds__(256) void k3b_reduce(
    const float* __restrict__ part, float* __restrict__ out)
{
    const int idx = blockIdx.x * 256 + threadIdx.x;   // 0 .. B*RNN-1
    const int stride = B_ * RNN_;                     // 262144

    float a0 = part[idx];
    float a1 = part[idx + stride];
    float a2 = part[idx + 2 * stride];
    float a3 = part[idx + 3 * stride];
    float a4 = part[idx + 4 * stride];
    float a5 = part[idx + 5 * stride];
    float a6 = part[idx + 6 * stride];
    out[idx] = ((a0 + a1) + (a2 + a3)) + ((a4 + a5) + a6);
}

// ---------------------------------------------------------------------------
extern "C" void kernel_launch(void* const* d_in, const int* in_sizes, int n_in,
                              void* d_out, int out_size)
{
    const float* h        = (const float*)d_in[0];  // [B, RNN]
    const float* att      = (const float*)d_in[1];  // [B, S, RNN]
    const float* p        = (const float*)d_in[2];  // [B, S, ATTH]
    const float* w_h2att  = (const float*)d_in[3];  // [ATTH, RNN]
    const float* b_h2att  = (const float*)d_in[4];  // [ATTH]
    const float* w_alpha  = (const float*)d_in[5];  // [1, ATTH]
    // d_in[6] = b_alpha: softmax-invariant, unused
    float* out = (float*)d_out;                     // [B, RNN]

    float *ahp_ptr = nullptr, *sc_ptr = nullptr, *part_ptr = nullptr;
    cudaGetSymbolAddress((void**)&ahp_ptr,  g_att_h_part);
    cudaGetSymbolAddress((void**)&sc_ptr,   g_scores);
    cudaGetSymbolAddress((void**)&part_ptr, g_part);

    k1_h2att<<<dim3(ATTH_ / 32, B_ / 32, KSPLIT), 256>>>(h, w_h2att, ahp_ptr);
    k2a_scores<<<dim3(B_, 4), 256>>>(p, ahp_ptr, b_h2att, w_alpha, sc_ptr);
    k3a_partial<<<dim3(B_, NSPLIT), 128>>>(att, sc_ptr, part_ptr);
    k3b_reduce<<<B_ * RNN_ / 256, 256>>>(part_ptr, out);
}

// round 7
// speedup vs baseline: 1.0224x; 1.0224x over previous
#include <cuda_runtime.h>
#include <math.h>

// Problem constants (fixed by the dataset)
#define B_    256
#define S_    196
#define RNN_  1024
#define ATTH_ 512
#define NSPLIT 7
#define SCHUNK 28   // 196 / 7
#define KSPLIT 2

// Scratch (allocation-free: __device__ globals)
__device__ float g_att_h_part[KSPLIT * B_ * ATTH_];  // 1 MB  (k1 partials)
__device__ float g_scores[B_ * S_];                  // 200 KB
__device__ float g_part[NSPLIT * B_ * RNN_];         // 7 MB  (k3 partials)
__device__ int   g_cnt[B_];                          // per-batch arrival tickets (zero-init)

// ---------------------------------------------------------------------------
// HW tanh: MUFU.TANH, single instruction, abs err ~5e-4 (scores only feed a
// softmax; resulting output rel err ~3e-6 measured, threshold 1e-3).
// ---------------------------------------------------------------------------
__device__ __forceinline__ float tanh_approx(float x)
{
    float y;
    asm("tanh.approx.f32 %0, %1;" : "=f"(y) : "f"(x));
    return y;
}

// ---------------------------------------------------------------------------
// K1: partial att_h: part[kz][b][a] = sum_{k in half kz} h[b,k] * W[a,k]
// 32x32 tiles, BK=32, split-k=2, double-buffered smem.
// grid = (16, 8, 2) = 256 blocks, 256 threads, 2x2 microtile.
// ---------------------------------------------------------------------------
__global__ __launch_bounds__(256) void k1_h2att(
    const float* __restrict__ h, const float* __restrict__ w,
    float* __restrict__ part)
{
    __shared__ float sh[2][32][34];
    __shared__ float sw[2][32][34];

    const int t  = threadIdx.x;
    const int a0 = blockIdx.x * 32;
    const int b0 = blockIdx.y * 32;
    const int kz = blockIdx.z;
    const int tx = t & 15;
    const int ty = t >> 4;
    const int lr = t >> 3;
    const int lc = (t & 7) * 4;

    const float* hrow = &h[(size_t)(b0 + lr) * RNN_ + (size_t)kz * (RNN_ / KSPLIT) + lc];
    const float* wrow = &w[(size_t)(a0 + lr) * RNN_ + (size_t)kz * (RNN_ / KSPLIT) + lc];

    float4 hv = *(const float4*)hrow;
    float4 wv = *(const float4*)wrow;
    sh[0][lc + 0][lr] = hv.x; sh[0][lc + 1][lr] = hv.y;
    sh[0][lc + 2][lr] = hv.z; sh[0][lc + 3][lr] = hv.w;
    sw[0][lc + 0][lr] = wv.x; sw[0][lc + 1][lr] = wv.y;
    sw[0][lc + 2][lr] = wv.z; sw[0][lc + 3][lr] = wv.w;
    __syncthreads();

    float acc00 = 0.f, acc01 = 0.f, acc10 = 0.f, acc11 = 0.f;

    const int NT = RNN_ / KSPLIT / 32;   // 16 k-tiles
    #pragma unroll
    for (int kt = 0; kt < NT; kt++) {
        const int buf = kt & 1;
        if (kt + 1 < NT) {
            hv = *(const float4*)(hrow + (kt + 1) * 32);
            wv = *(const float4*)(wrow + (kt + 1) * 32);
        }
        #pragma unroll
        for (int kk = 0; kk < 32; kk++) {
            float2 hb = *(const float2*)&sh[buf][kk][ty * 2];
            float2 wb = *(const float2*)&sw[buf][kk][tx * 2];
            acc00 += hb.x * wb.x;
            acc01 += hb.x * wb.y;
            acc10 += hb.y * wb.x;
            acc11 += hb.y * wb.y;
        }
        __syncthreads();
        if (kt + 1 < NT) {
            const int nb = buf ^ 1;
            sh[nb][lc + 0][lr] = hv.x; sh[nb][lc + 1][lr] = hv.y;
            sh[nb][lc + 2][lr] = hv.z; sh[nb][lc + 3][lr] = hv.w;
            sw[nb][lc + 0][lr] = wv.x; sw[nb][lc + 1][lr] = wv.y;
            sw[nb][lc + 2][lr] = wv.z; sw[nb][lc + 3][lr] = wv.w;
            __syncthreads();
        }
    }

    const int bb = b0 + ty * 2;
    const int aa = a0 + tx * 2;
    float* op = part + (size_t)kz * B_ * ATTH_;
    op[(size_t)bb * ATTH_ + aa]           = acc00;
    op[(size_t)bb * ATTH_ + aa + 1]       = acc01;
    op[(size_t)(bb + 1) * ATTH_ + aa]     = acc10;
    op[(size_t)(bb + 1) * ATTH_ + aa + 1] = acc11;
}

// ---------------------------------------------------------------------------
// score of one s-row given its 4 float4 values (v[i] covers a = lane+32i,x4)
// ---------------------------------------------------------------------------
__device__ __forceinline__ float row_score(
    const float4 v[4], const float4* __restrict__ ah4,
    const float4* __restrict__ wa4, int lane)
{
    float acc = 0.f;
    #pragma unroll
    for (int i = 0; i < 4; i++) {
        float4 a  = ah4[lane + i * 32];
        float4 wv = wa4[lane + i * 32];
        acc += tanh_approx(v[i].x + a.x) * wv.x + tanh_approx(v[i].y + a.y) * wv.y
             + tanh_approx(v[i].z + a.z) * wv.z + tanh_approx(v[i].w + a.w) * wv.w;
    }
    return acc;
}

__device__ __forceinline__ void load_row(
    float4 v[4], const float4* __restrict__ ps, int lane)
{
    v[0] = __ldcs(&ps[lane]);
    v[1] = __ldcs(&ps[lane + 32]);
    v[2] = __ldcs(&ps[lane + 64]);
    v[3] = __ldcs(&ps[lane + 96]);
}

// ---------------------------------------------------------------------------
// K2a: scores[b,s] = sum_a tanh(p[b,s,a] + att_h[b,a]) * w_alpha[a]
// att_h assembled in smem from the two k1 partials + bias.
// grid = (B, 4), 256 threads. Warp processes 3 row-pairs, SOFTWARE-PIPELINED:
// the next pair's 8 float4 loads are issued before computing the current
// pair, so DRAM latency hides behind the tanh chain.
// ---------------------------------------------------------------------------
__global__ __launch_bounds__(256) void k2a_scores(
    const float* __restrict__ p, const float* __restrict__ att_h_part,
    const float* __restrict__ bias, const float* __restrict__ w_alpha,
    float* __restrict__ scores)
{
    const int b     = blockIdx.x;
    const int chunk = blockIdx.y;
    const int t     = threadIdx.x;

    __shared__ float4 ah4[ATTH_ / 4];
    __shared__ float4 wa4[ATTH_ / 4];
    {
        const float4* p0 = (const float4*)(att_h_part + (size_t)b * ATTH_);
        const float4* p1 = (const float4*)(att_h_part + (size_t)(B_ + b) * ATTH_);
        const float4* bz = (const float4*)bias;
        for (int i = t; i < ATTH_ / 4; i += 256) {
            float4 x = p0[i], y = p1[i], z = bz[i];
            ah4[i] = make_float4(x.x + y.x + z.x, x.y + y.y + z.y,
                                 x.z + y.z + z.z, x.w + y.w + z.w);
            wa4[i] = ((const float4*)w_alpha)[i];
        }
    }
    __syncthreads();

    const int warp = t >> 5, lane = t & 31;
    const int s_lo = chunk * 49;
    const float4* pb = (const float4*)(p + (size_t)b * S_ * ATTH_);

    float4 curU[4], curQ[4], tailV[4];

    // prologue: loads for pair 0 (rows s0, s0+1) + tail row (warp 0 only)
    {
        const int s = s_lo + warp * 2;
        load_row(curU, pb + (size_t)s * (ATTH_ / 4), lane);
        load_row(curQ, pb + (size_t)(s + 1) * (ATTH_ / 4), lane);
    }
    if (warp == 0)
        load_row(tailV, pb + (size_t)(s_lo + 48) * (ATTH_ / 4), lane);

    #pragma unroll
    for (int it = 0; it < 3; it++) {
        const int s = s_lo + (warp + 8 * it) * 2;
        float4 nU[4], nQ[4];
        if (it < 2) {                                  // prefetch next pair
            const int sn = s_lo + (warp + 8 * (it + 1)) * 2;
            load_row(nU, pb + (size_t)sn * (ATTH_ / 4), lane);
            load_row(nQ, pb + (size_t)(sn + 1) * (ATTH_ / 4), lane);
        }
        float accA = row_score(curU, ah4, wa4, lane);
        float accB = row_score(curQ, ah4, wa4, lane);
        #pragma unroll
        for (int o = 16; o; o >>= 1) {
            accA += __shfl_xor_sync(0xffffffffu, accA, o);
            accB += __shfl_xor_sync(0xffffffffu, accB, o);
        }
        if (lane == 0) {
            scores[(size_t)b * S_ + s]     = accA;
            scores[(size_t)b * S_ + s + 1] = accB;
        }
        if (it < 2) {
            #pragma unroll
            for (int i = 0; i < 4; i++) { curU[i] = nU[i]; curQ[i] = nQ[i]; }
        }
    }

    // tail row (chunk-local row 48), loads already in flight since prologue
    if (warp == 0) {
        float acc = row_score(tailV, ah4, wa4, lane);
        #pragma unroll
        for (int o = 16; o; o >>= 1)
            acc += __shfl_xor_sync(0xffffffffu, acc, o);
        if (lane == 0) scores[(size_t)b * S_ + s_lo + 48] = acc;
    }
}

// ---------------------------------------------------------------------------
// K3a: partial weighted sums with fused (recomputed, deterministic) softmax,
// PLUS fused final reduction: the last-arriving block per batch sums the 7
// partials (fixed order -> deterministic) and writes out[b,:]. Ticket counter
// self-resets for graph replay.
// grid = (B, NSPLIT) = 1792 blocks, 128 threads; thread owns TWO float4 cols.
// ---------------------------------------------------------------------------
__global__ __launch_bounds__(128) void k3a_partial(
    const float* __restrict__ att, const float* __restrict__ scores,
    float* __restrict__ part, float* __restrict__ out)
{
    const int b     = blockIdx.x;
    const int split = blockIdx.y;
    const int t     = threadIdx.x;
    const int s_lo  = split * SCHUNK;

    __shared__ float es[S_];
    __shared__ float red[128];
    __shared__ float w_s[SCHUNK];
    __shared__ int   is_last;

    // --- inline softmax over scores[b, 0..195] ---
    float v0 = (t < S_)       ? scores[(size_t)b * S_ + t]       : -INFINITY;
    float v1 = (t + 128 < S_) ? scores[(size_t)b * S_ + t + 128] : -INFINITY;
    red[t] = fmaxf(v0, v1);
    __syncthreads();
    #pragma unroll
    for (int o = 64; o; o >>= 1) {
        if (t < o) red[t] = fmaxf(red[t], red[t + o]);
        __syncthreads();
    }
    const float m = red[0];
    __syncthreads();
    float e0 = (t < S_)       ? __expf(v0 - m) : 0.f;
    float e1 = (t + 128 < S_) ? __expf(v1 - m) : 0.f;
    if (t < S_)       es[t]       = e0;
    if (t + 128 < S_) es[t + 128] = e1;
    red[t] = e0 + e1;
    __syncthreads();
    #pragma unroll
    for (int o = 64; o; o >>= 1) {
        if (t < o) red[t] += red[t + o];
        __syncthreads();
    }
    const float inv = 1.f / red[0];
    __syncthreads();
    if (t < SCHUNK) w_s[t] = es[s_lo + t] * inv;
    __syncthreads();

    // --- weighted partial sum, 2 float4 columns per thread ---
    const float4* ap = (const float4*)(att + ((size_t)b * S_ + s_lo) * RNN_);
    float4 acc0 = make_float4(0.f, 0.f, 0.f, 0.f);
    float4 acc1 = make_float4(0.f, 0.f, 0.f, 0.f);
    #pragma unroll 7
    for (int s = 0; s < SCHUNK; s++) {
        const float w = w_s[s];
        const float4 va = __ldcs(&ap[(size_t)s * (RNN_ / 4) + t]);
        const float4 vb = __ldcs(&ap[(size_t)s * (RNN_ / 4) + t + 128]);
        acc0.x += w * va.x; acc0.y += w * va.y;
        acc0.z += w * va.z; acc0.w += w * va.w;
        acc1.x += w * vb.x; acc1.y += w * vb.y;
        acc1.z += w * vb.z; acc1.w += w * vb.w;
    }
    float4* op = (float4*)(part + ((size_t)split * B_ + b) * RNN_);
    op[t]       = acc0;
    op[t + 128] = acc1;

    // --- last-block-per-batch final reduction (threadFenceReduction pattern)
    __threadfence();
    __syncthreads();
    if (t == 0) {
        int ticket = atomicAdd(&g_cnt[b], 1);
        is_last = (ticket == NSPLIT - 1) ? 1 : 0;
        if (is_last) g_cnt[b] = 0;   // reset for next graph replay
    }
    __syncthreads();

    if (is_last) {
        float4* ob = (float4*)(out + (size_t)b * RNN_);
        #pragma unroll
        for (int j = 0; j < 2; j++) {
            const int c4 = t + j * 128;   // float4 column 0..255
            float4 r = make_float4(0.f, 0.f, 0.f, 0.f);
            #pragma unroll
            for (int sp = 0; sp < NSPLIT; sp++) {
                const float4 v =
                    ((const float4*)(part + ((size_t)sp * B_ + b) * RNN_))[c4];
                r.x += v.x; r.y += v.y; r.z += v.z; r.w += v.w;
            }
            ob[c4] = r;
        }
    }
}

// ---------------------------------------------------------------------------
extern "C" void kernel_launch(void* const* d_in, const int* in_sizes, int n_in,
                              void* d_out, int out_size)
{
    const float* h        = (const float*)d_in[0];  // [B, RNN]
    const float* att      = (const float*)d_in[1];  // [B, S, RNN]
    const float* p        = (const float*)d_in[2];  // [B, S, ATTH]
    const float* w_h2att  = (const float*)d_in[3];  // [ATTH, RNN]
    const float* b_h2att  = (const float*)d_in[4];  // [ATTH]
    const float* w_alpha  = (const float*)d_in[5];  // [1, ATTH]
    // d_in[6] = b_alpha: softmax-invariant, unused
    float* out = (float*)d_out;                     // [B, RNN]

    float *ahp_ptr = nullptr, *sc_ptr = nullptr, *part_ptr = nullptr;
    cudaGetSymbolAddress((void**)&ahp_ptr,  g_att_h_part);
    cudaGetSymbolAddress((void**)&sc_ptr,   g_scores);
    cudaGetSymbolAddress((void**)&part_ptr, g_part);

    k1_h2att<<<dim3(ATTH_ / 32, B_ / 32, KSPLIT), 256>>>(h, w_h2att, ahp_ptr);
    k2a_scores<<<dim3(B_, 4), 256>>>(p, ahp_ptr, b_h2att, w_alpha, sc_ptr);
    k3a_partial<<<dim3(B_, NSPLIT), 128>>>(att, sc_ptr, part_ptr, out);
}

// round 8
// speedup vs baseline: 1.1135x; 1.0891x over previous
#include <cuda_runtime.h>
#include <math.h>

// Problem constants (fixed by the dataset)
#define B_    256
#define S_    196
#define RNN_  1024
#define ATTH_ 512
#define NSPLIT 7
#define SCHUNK 28   // 196 / 7
#define KSPLIT 8    // k1 split-k factor

// Scratch (allocation-free: __device__ globals)
__device__ float g_att_h_part[KSPLIT * B_ * ATTH_];  // 4 MB  (k1 partials)
__device__ float g_scores[B_ * S_];                  // 200 KB
__device__ float g_part[NSPLIT * B_ * RNN_];         // 7 MB  (k3 partials)
__device__ int   g_cnt[B_];                          // per-batch tickets (zero-init)

// ---------------------------------------------------------------------------
// HW tanh: MUFU.TANH (abs err ~5e-4; output rel err measured ~3e-6, gate 1e-3)
// ---------------------------------------------------------------------------
__device__ __forceinline__ float tanh_approx(float x)
{
    float y;
    asm("tanh.approx.f32 %0, %1;" : "=f"(y) : "f"(x));
    return y;
}

// ---------------------------------------------------------------------------
// K1: partial att_h: part[kz][b][a] = sum_{k in chunk kz} h[b,k] * W[a,k]
// 64x64 tile, BK=32, 4x4 microtile (0.5 FMA/LDS-byte: crossbar & FMA pipe
// balanced), double-buffered smem, split-k=8.
// grid = (ATTH/64, B/64, KSPLIT) = (8, 4, 8) = 256 blocks, 256 threads.
// ---------------------------------------------------------------------------
__global__ __launch_bounds__(256) void k1_h2att(
    const float* __restrict__ h, const float* __restrict__ w,
    float* __restrict__ part)
{
    __shared__ float sh[2][32][68];   // [buf][k][b]  (68: 16B-aligned rows, low conflict)
    __shared__ float sw[2][32][68];   // [buf][k][a]

    const int t  = threadIdx.x;
    const int a0 = blockIdx.x * 64;
    const int b0 = blockIdx.y * 64;
    const int kz = blockIdx.z;
    const int tx = t & 15;            // a-dim (x4)
    const int ty = t >> 4;            // b-dim (x4)

    // global-load mapping: 2 float4 per array per thread per tile
    const int lr = t >> 3;            // 0..31
    const int lc = (t & 7) * 4;       // 0,4,..,28

    const size_t kbase = (size_t)kz * (RNN_ / KSPLIT);
    const float* h0 = &h[(size_t)(b0 + lr) * RNN_ + kbase + lc];
    const float* h1 = &h[(size_t)(b0 + lr + 32) * RNN_ + kbase + lc];
    const float* w0 = &w[(size_t)(a0 + lr) * RNN_ + kbase + lc];
    const float* w1 = &w[(size_t)(a0 + lr + 32) * RNN_ + kbase + lc];

    // preload tile 0
    float4 hA = *(const float4*)h0;
    float4 hB = *(const float4*)h1;
    float4 wA = *(const float4*)w0;
    float4 wB = *(const float4*)w1;
    #pragma unroll
    for (int c = 0; c < 4; c++) {
        sh[0][lc + c][lr]      = (&hA.x)[c];
        sh[0][lc + c][lr + 32] = (&hB.x)[c];
        sw[0][lc + c][lr]      = (&wA.x)[c];
        sw[0][lc + c][lr + 32] = (&wB.x)[c];
    }
    __syncthreads();

    float acc[4][4] = {};

    const int NT = RNN_ / KSPLIT / 32;   // 4 k-tiles
    #pragma unroll
    for (int kt = 0; kt < NT; kt++) {
        const int buf = kt & 1;
        if (kt + 1 < NT) {               // prefetch next tile into registers
            hA = *(const float4*)(h0 + (kt + 1) * 32);
            hB = *(const float4*)(h1 + (kt + 1) * 32);
            wA = *(const float4*)(w0 + (kt + 1) * 32);
            wB = *(const float4*)(w1 + (kt + 1) * 32);
        }
        #pragma unroll
        for (int kk = 0; kk < 32; kk++) {
            float4 hv = *(const float4*)&sh[buf][kk][ty * 4];
            float4 wv = *(const float4*)&sw[buf][kk][tx * 4];
            #pragma unroll
            for (int i = 0; i < 4; i++)
                #pragma unroll
                for (int j = 0; j < 4; j++)
                    acc[i][j] += (&hv.x)[i] * (&wv.x)[j];
        }
        __syncthreads();
        if (kt + 1 < NT) {
            const int nb = buf ^ 1;
            #pragma unroll
            for (int c = 0; c < 4; c++) {
                sh[nb][lc + c][lr]      = (&hA.x)[c];
                sh[nb][lc + c][lr + 32] = (&hB.x)[c];
                sw[nb][lc + c][lr]      = (&wA.x)[c];
                sw[nb][lc + c][lr + 32] = (&wB.x)[c];
            }
            __syncthreads();
        }
    }

    float* op = part + (size_t)kz * B_ * ATTH_;
    #pragma unroll
    for (int i = 0; i < 4; i++) {
        const int bb = b0 + ty * 4 + i;
        float4 r = make_float4(acc[i][0], acc[i][1], acc[i][2], acc[i][3]);
        *(float4*)&op[(size_t)bb * ATTH_ + a0 + tx * 4] = r;
    }
}

// ---------------------------------------------------------------------------
// helpers for k2a
// ---------------------------------------------------------------------------
__device__ __forceinline__ float row_score(
    const float4 v[4], const float4* __restrict__ ah4,
    const float4* __restrict__ wa4, int lane)
{
    float acc = 0.f;
    #pragma unroll
    for (int i = 0; i < 4; i++) {
        float4 a  = ah4[lane + i * 32];
        float4 wv = wa4[lane + i * 32];
        acc += tanh_approx(v[i].x + a.x) * wv.x + tanh_approx(v[i].y + a.y) * wv.y
             + tanh_approx(v[i].z + a.z) * wv.z + tanh_approx(v[i].w + a.w) * wv.w;
    }
    return acc;
}

__device__ __forceinline__ void load_row(
    float4 v[4], const float4* __restrict__ ps, int lane)
{
    v[0] = __ldcs(&ps[lane]);
    v[1] = __ldcs(&ps[lane + 32]);
    v[2] = __ldcs(&ps[lane + 64]);
    v[3] = __ldcs(&ps[lane + 96]);
}

// ---------------------------------------------------------------------------
// K2a: scores[b,s] = sum_a tanh(p[b,s,a] + att_h[b,a]) * w_alpha[a]
// att_h assembled in smem from the KSPLIT k1 partials + bias.
// grid = (B, 4), 256 threads; warp handles 3 row-pairs, software-pipelined.
// ---------------------------------------------------------------------------
__global__ __launch_bounds__(256) void k2a_scores(
    const float* __restrict__ p, const float* __restrict__ att_h_part,
    const float* __restrict__ bias, const float* __restrict__ w_alpha,
    float* __restrict__ scores)
{
    const int b     = blockIdx.x;
    const int chunk = blockIdx.y;
    const int t     = threadIdx.x;

    __shared__ float4 ah4[ATTH_ / 4];
    __shared__ float4 wa4[ATTH_ / 4];
    if (t < ATTH_ / 4) {
        float4 r = ((const float4*)bias)[t];
        #pragma unroll
        for (int kz = 0; kz < KSPLIT; kz++) {
            const float4 v = ((const float4*)(att_h_part
                + ((size_t)kz * B_ + b) * ATTH_))[t];
            r.x += v.x; r.y += v.y; r.z += v.z; r.w += v.w;
        }
        ah4[t] = r;
        wa4[t] = ((const float4*)w_alpha)[t];
    }
    __syncthreads();

    const int warp = t >> 5, lane = t & 31;
    const int s_lo = chunk * 49;
    const float4* pb = (const float4*)(p + (size_t)b * S_ * ATTH_);

    float4 curU[4], curQ[4], tailV[4];

    {
        const int s = s_lo + warp * 2;
        load_row(curU, pb + (size_t)s * (ATTH_ / 4), lane);
        load_row(curQ, pb + (size_t)(s + 1) * (ATTH_ / 4), lane);
    }
    if (warp == 0)
        load_row(tailV, pb + (size_t)(s_lo + 48) * (ATTH_ / 4), lane);

    #pragma unroll
    for (int it = 0; it < 3; it++) {
        const int s = s_lo + (warp + 8 * it) * 2;
        float4 nU[4], nQ[4];
        if (it < 2) {
            const int sn = s_lo + (warp + 8 * (it + 1)) * 2;
            load_row(nU, pb + (size_t)sn * (ATTH_ / 4), lane);
            load_row(nQ, pb + (size_t)(sn + 1) * (ATTH_ / 4), lane);
        }
        float accA = row_score(curU, ah4, wa4, lane);
        float accB = row_score(curQ, ah4, wa4, lane);
        #pragma unroll
        for (int o = 16; o; o >>= 1) {
            accA += __shfl_xor_sync(0xffffffffu, accA, o);
            accB += __shfl_xor_sync(0xffffffffu, accB, o);
        }
        if (lane == 0) {
            scores[(size_t)b * S_ + s]     = accA;
            scores[(size_t)b * S_ + s + 1] = accB;
        }
        if (it < 2) {
            #pragma unroll
            for (int i = 0; i < 4; i++) { curU[i] = nU[i]; curQ[i] = nQ[i]; }
        }
    }

    if (warp == 0) {
        float acc = row_score(tailV, ah4, wa4, lane);
        #pragma unroll
        for (int o = 16; o; o >>= 1)
            acc += __shfl_xor_sync(0xffffffffu, acc, o);
        if (lane == 0) scores[(size_t)b * S_ + s_lo + 48] = acc;
    }
}

// ---------------------------------------------------------------------------
// K3a: partial weighted sums with fused softmax + fused last-block reduce.
// grid = (B, NSPLIT) = 1792 blocks, 128 threads; thread owns TWO float4 cols.
// ---------------------------------------------------------------------------
__global__ __launch_bounds__(128) void k3a_partial(
    const float* __restrict__ att, const float* __restrict__ scores,
    float* __restrict__ part, float* __restrict__ out)
{
    const int b     = blockIdx.x;
    const int split = blockIdx.y;
    const int t     = threadIdx.x;
    const int s_lo  = split * SCHUNK;

    __shared__ float es[S_];
    __shared__ float red[128];
    __shared__ float w_s[SCHUNK];
    __shared__ int   is_last;

    // --- inline softmax over scores[b, 0..195] (deterministic per block) ---
    float v0 = (t < S_)       ? scores[(size_t)b * S_ + t]       : -INFINITY;
    float v1 = (t + 128 < S_) ? scores[(size_t)b * S_ + t + 128] : -INFINITY;
    red[t] = fmaxf(v0, v1);
    __syncthreads();
    #pragma unroll
    for (int o = 64; o; o >>= 1) {
        if (t < o) red[t] = fmaxf(red[t], red[t + o]);
        __syncthreads();
    }
    const float m = red[0];
    __syncthreads();
    float e0 = (t < S_)       ? __expf(v0 - m) : 0.f;
    float e1 = (t + 128 < S_) ? __expf(v1 - m) : 0.f;
    if (t < S_)       es[t]       = e0;
    if (t + 128 < S_) es[t + 128] = e1;
    red[t] = e0 + e1;
    __syncthreads();
    #pragma unroll
    for (int o = 64; o; o >>= 1) {
        if (t < o) red[t] += red[t + o];
        __syncthreads();
    }
    const float inv = 1.f / red[0];
    __syncthreads();
    if (t < SCHUNK) w_s[t] = es[s_lo + t] * inv;
    __syncthreads();

    // --- weighted partial sum, 2 float4 columns per thread ---
    const float4* ap = (const float4*)(att + ((size_t)b * S_ + s_lo) * RNN_);
    float4 acc0 = make_float4(0.f, 0.f, 0.f, 0.f);
    float4 acc1 = make_float4(0.f, 0.f, 0.f, 0.f);
    #pragma unroll 7
    for (int s = 0; s < SCHUNK; s++) {
        const float w = w_s[s];
        const float4 va = __ldcs(&ap[(size_t)s * (RNN_ / 4) + t]);
        const float4 vb = __ldcs(&ap[(size_t)s * (RNN_ / 4) + t + 128]);
        acc0.x += w * va.x; acc0.y += w * va.y;
        acc0.z += w * va.z; acc0.w += w * va.w;
        acc1.x += w * vb.x; acc1.y += w * vb.y;
        acc1.z += w * vb.z; acc1.w += w * vb.w;
    }
    float4* op = (float4*)(part + ((size_t)split * B_ + b) * RNN_);
    op[t]       = acc0;
    op[t + 128] = acc1;

    // --- last-block-per-batch final reduction (threadfence pattern) ---
    __threadfence();
    __syncthreads();
    if (t == 0) {
        int ticket = atomicAdd(&g_cnt[b], 1);
        is_last = (ticket == NSPLIT - 1) ? 1 : 0;
        if (is_last) g_cnt[b] = 0;   // reset for next graph replay
    }
    __syncthreads();

    if (is_last) {
        float4* ob = (float4*)(out + (size_t)b * RNN_);
        #pragma unroll
        for (int j = 0; j < 2; j++) {
            const int c4 = t + j * 128;   // float4 column 0..255
            float4 r = make_float4(0.f, 0.f, 0.f, 0.f);
            #pragma unroll
            for (int sp = 0; sp < NSPLIT; sp++) {
                const float4 v = __ldcg(
                    (const float4*)(part + ((size_t)sp * B_ + b) * RNN_) + c4);
                r.x += v.x; r.y += v.y; r.z += v.z; r.w += v.w;
            }
            ob[c4] = r;
        }
    }
}

// ---------------------------------------------------------------------------
extern "C" void kernel_launch(void* const* d_in, const int* in_sizes, int n_in,
                              void* d_out, int out_size)
{
    const float* h        = (const float*)d_in[0];  // [B, RNN]
    const float* att      = (const float*)d_in[1];  // [B, S, RNN]
    const float* p        = (const float*)d_in[2];  // [B, S, ATTH]
    const float* w_h2att  = (const float*)d_in[3];  // [ATTH, RNN]
    const float* b_h2att  = (const float*)d_in[4];  // [ATTH]
    const float* w_alpha  = (const float*)d_in[5];  // [1, ATTH]
    // d_in[6] = b_alpha: softmax-invariant, unused
    float* out = (float*)d_out;                     // [B, RNN]

    float *ahp_ptr = nullptr, *sc_ptr = nullptr, *part_ptr = nullptr;
    cudaGetSymbolAddress((void**)&ahp_ptr,  g_att_h_part);
    cudaGetSymbolAddress((void**)&sc_ptr,   g_scores);
    cudaGetSymbolAddress((void**)&part_ptr, g_part);

    k1_h2att<<<dim3(ATTH_ / 64, B_ / 64, KSPLIT), 256>>>(h, w_h2att, ahp_ptr);
    k2a_scores<<<dim3(B_, 4), 256>>>(p, ahp_ptr, b_h2att, w_alpha, sc_ptr);
    k3a_partial<<<dim3(B_, NSPLIT), 128>>>(att, sc_ptr, part_ptr, out);
}